// round 9
// baseline (speedup 1.0000x reference)
#include <cuda_runtime.h>
#include <cuda_bf16.h>

typedef unsigned long long ull;

#define NTOK 8192   // B*T
#define DDIM 2048
#define NEXP 8
#define IDIM 6144
#define RDIM 32
#define ERD  256    // NEXP*RDIM

// ---------------- scratch (static device allocations are the sanctioned path) ----
__device__ int   g_idx[NTOK];
__device__ float g_AgT[DDIM * ERD];           // A_gate transposed to [D, E*R]
__device__ float g_AuT[DDIM * ERD];
__device__ float g_tg[NTOK * ERD];            // masked lora activations (gate)
__device__ float g_tu[NTOK * ERD];            // masked lora activations (up)
__device__ float g_G[(size_t)NTOK * IDIM];    // gate pre-activation
__device__ float g_H[(size_t)NTOK * IDIM];    // silu(gate)*up
__device__ float g_logits_scratch[NTOK * NEXP];

// ---------------- f32x2 helpers (Blackwell packed fp32) --------------------------
__device__ __forceinline__ ull pk2(float x, float y) {
    ull r;
    asm("mov.b64 %0, {%1,%2};" : "=l"(r) : "f"(x), "f"(y));
    return r;
}
__device__ __forceinline__ void upk2(ull v, float& x, float& y) {
    asm("mov.b64 {%0,%1}, %2;" : "=f"(x), "=f"(y) : "l"(v));
}
__device__ __forceinline__ void fma2(ull& d, ull a, ull b) {
    asm("fma.rn.f32x2 %0, %1, %2, %0;" : "+l"(d) : "l"(a), "l"(b));
}

// ---------------- router: logits + argmax (first-max, matches jnp.argmax) --------
__global__ void router_kernel(const float* __restrict__ x,
                              const float* __restrict__ rw,
                              int* __restrict__ idx,
                              float* __restrict__ logits) {
    int gwarp = (blockIdx.x * blockDim.x + threadIdx.x) >> 5;
    int lane = threadIdx.x & 31;
    if (gwarp >= NTOK) return;
    const float* xp = x + (size_t)gwarp * DDIM;
    float acc[NEXP];
#pragma unroll
    for (int e = 0; e < NEXP; e++) acc[e] = 0.f;
    for (int d = lane; d < DDIM; d += 32) {
        float xv = xp[d];
        const float4* w4 = reinterpret_cast<const float4*>(rw + (size_t)d * NEXP);
        float4 w0 = w4[0], w1 = w4[1];
        acc[0] += xv * w0.x; acc[1] += xv * w0.y;
        acc[2] += xv * w0.z; acc[3] += xv * w0.w;
        acc[4] += xv * w1.x; acc[5] += xv * w1.y;
        acc[6] += xv * w1.z; acc[7] += xv * w1.w;
    }
#pragma unroll
    for (int e = 0; e < NEXP; e++) {
#pragma unroll
        for (int off = 16; off > 0; off >>= 1)
            acc[e] += __shfl_xor_sync(0xffffffffu, acc[e], off);
    }
    if (lane == 0) {
        int best = 0; float bv = acc[0];
#pragma unroll
        for (int e = 1; e < NEXP; e++)
            if (acc[e] > bv) { bv = acc[e]; best = e; }
        idx[gwarp] = best;
#pragma unroll
        for (int e = 0; e < NEXP; e++) logits[gwarp * NEXP + e] = acc[e];
    }
}

// ---------------- transpose A: [E, D, R] -> [D, E*R] -----------------------------
__global__ void transposeA_kernel(const float* __restrict__ Ag,
                                  const float* __restrict__ Au,
                                  float* __restrict__ AgT,
                                  float* __restrict__ AuT) {
    int i = blockIdx.x * blockDim.x + threadIdx.x;
    if (i >= NEXP * DDIM * RDIM) return;
    int r = i & (RDIM - 1);
    int d = (i >> 5) & (DDIM - 1);   // D*R = 65536 = 2^16, R = 32 = 2^5
    int e = i >> 16;
    int o = d * ERD + e * RDIM + r;
    AgT[o] = Ag[i];
    AuT[o] = Au[i];
}

// ---------------- generic SGEMM (f32x2), 128x128x16 tile, 8x8/thread -------------
// C[M,ND] = concat_K(A1[M,K1], A2[M,K2]) @ concat_K(B1[K1,ND], B2[K2,ND])
// MODE 0: plain store
// MODE 1: out = silu(Gprev) * acc          (fused SwiGLU)
// MODE 3: out = acc masked to token's expert (column block of 32 = expert id)
template<int KTOT, int K1, int ND, int MODE>
__global__ void __launch_bounds__(256)
gemm_kernel(const float* __restrict__ A1,
            const float* __restrict__ A2,
            const float* __restrict__ B1,
            const float* __restrict__ B2,
            const int* __restrict__ idx,
            const float* __restrict__ Gprev,
            float* __restrict__ out) {
    constexpr int BM = 128, BN = 128, BK = 16;
    constexpr int K2 = KTOT - K1;
    // A staged as duplicated (a,a) 64-bit pairs, row padded to 130 (1040B: 16B-aligned,
    // bank-shifted) so inner-loop reads need zero MOVs and stores are conflict-light.
    __shared__ ull   As2[BK][BM + 2];
    __shared__ float Bs[BK][BN];

    const int tid = threadIdx.x;
    const int row0 = blockIdx.y * BM;
    const int col0 = blockIdx.x * BN;
    const int tr = tid >> 4;          // 0..15
    const int tc = tid & 15;          // 0..15

    const int a_r = tid >> 2;         // 0..63
    const int a_c = (tid & 3) << 2;   // 0,4,8,12
    const int b_r = tid >> 5;         // 0..7
    const int b_c = (tid & 31) << 2;  // 0..124

    ull acc[8][4];
#pragma unroll
    for (int i = 0; i < 8; i++)
#pragma unroll
        for (int j = 0; j < 4; j++) acc[i][j] = 0ull;

    float4 aReg[2], bReg[2];

    auto loadAB = [&](int kc) {
#pragma unroll
        for (int it = 0; it < 2; it++) {
            int r = row0 + it * 64 + a_r;
            const float* pa;
            if (K2 == 0 || kc < K1)
                pa = A1 + (size_t)r * K1 + kc + a_c;
            else
                pa = A2 + (size_t)r * K2 + (kc - K1) + a_c;
            aReg[it] = *reinterpret_cast<const float4*>(pa);
        }
#pragma unroll
        for (int it = 0; it < 2; it++) {
            int kr = kc + it * 8 + b_r;
            const float* pb;
            if (K2 == 0 || kc < K1)
                pb = B1 + (size_t)kr * ND + col0 + b_c;
            else
                pb = B2 + (size_t)(kr - K1) * ND + col0 + b_c;
            bReg[it] = *reinterpret_cast<const float4*>(pb);
        }
    };

    loadAB(0);

    for (int kc = 0;;) {
        // commit prefetched tiles to smem
#pragma unroll
        for (int it = 0; it < 2; it++) {
            int r = it * 64 + a_r;
            As2[a_c + 0][r] = pk2(aReg[it].x, aReg[it].x);
            As2[a_c + 1][r] = pk2(aReg[it].y, aReg[it].y);
            As2[a_c + 2][r] = pk2(aReg[it].z, aReg[it].z);
            As2[a_c + 3][r] = pk2(aReg[it].w, aReg[it].w);
            *reinterpret_cast<float4*>(&Bs[it * 8 + b_r][b_c]) = bReg[it];
        }
        __syncthreads();

        int knext = kc + BK;
        if (knext < KTOT) loadAB(knext);

#pragma unroll
        for (int k = 0; k < BK; k++) {
            ulonglong2 aq0 = *reinterpret_cast<const ulonglong2*>(&As2[k][tr * 4]);
            ulonglong2 aq1 = *reinterpret_cast<const ulonglong2*>(&As2[k][tr * 4 + 2]);
            ulonglong2 aq2 = *reinterpret_cast<const ulonglong2*>(&As2[k][64 + tr * 4]);
            ulonglong2 aq3 = *reinterpret_cast<const ulonglong2*>(&As2[k][64 + tr * 4 + 2]);
            ulonglong2 bq0 = *reinterpret_cast<const ulonglong2*>(&Bs[k][tc * 4]);
            ulonglong2 bq1 = *reinterpret_cast<const ulonglong2*>(&Bs[k][64 + tc * 4]);
            ull a2[8] = {aq0.x, aq0.y, aq1.x, aq1.y, aq2.x, aq2.y, aq3.x, aq3.y};
            ull b2[4] = {bq0.x, bq0.y, bq1.x, bq1.y};
#pragma unroll
            for (int i = 0; i < 8; i++)
#pragma unroll
                for (int j = 0; j < 4; j++) fma2(acc[i][j], a2[i], b2[j]);
        }

        if (knext >= KTOT) break;
        __syncthreads();
        kc = knext;
    }

    // epilogue
    const int cbase0 = col0 + tc * 4;
    const int cbase1 = col0 + 64 + tc * 4;
    const int ce0 = cbase0 >> 5;    // expert id of column block (MODE 3)
    const int ce1 = cbase1 >> 5;

#pragma unroll
    for (int i = 0; i < 8; i++) {
        int row = row0 + (i < 4 ? tr * 4 + i : 64 + tr * 4 + (i - 4));
        float c[8];
        upk2(acc[i][0], c[0], c[1]);
        upk2(acc[i][1], c[2], c[3]);
        upk2(acc[i][2], c[4], c[5]);
        upk2(acc[i][3], c[6], c[7]);
        size_t base0 = (size_t)row * ND + cbase0;
        size_t base1 = (size_t)row * ND + cbase1;
        if (MODE == 3) {
            int e = idx[row];
            float k0 = (e == ce0) ? 1.f : 0.f;
            float k1 = (e == ce1) ? 1.f : 0.f;
#pragma unroll
            for (int j = 0; j < 4; j++) { c[j] *= k0; c[4 + j] *= k1; }
        }
        if (MODE == 1) {
#pragma unroll
            for (int j = 0; j < 4; j++) {
                float g = Gprev[base0 + j];
                c[j] *= g / (1.f + __expf(-g));
            }
#pragma unroll
            for (int j = 0; j < 4; j++) {
                float g = Gprev[base1 + j];
                c[4 + j] *= g / (1.f + __expf(-g));
            }
        }
        *reinterpret_cast<float4*>(out + base0) = make_float4(c[0], c[1], c[2], c[3]);
        *reinterpret_cast<float4*>(out + base1) = make_float4(c[4], c[5], c[6], c[7]);
    }
}

// ---------------- launch ----------------------------------------------------------
extern "C" void kernel_launch(void* const* d_in, const int* in_sizes, int n_in,
                              void* d_out, int out_size) {
    const float* x  = (const float*)d_in[0];
    const float* rw = (const float*)d_in[1];
    const float* Ag = (const float*)d_in[2];
    const float* Bg = (const float*)d_in[3];   // [E,R,I] == [256, 6144]
    const float* Au = (const float*)d_in[4];
    const float* Bu = (const float*)d_in[5];
    const float* Wg = (const float*)d_in[6];
    const float* Wu = (const float*)d_in[7];
    const float* Wd = (const float*)d_in[8];
    float* out = (float*)d_out;

    void* p;
    cudaGetSymbolAddress(&p, g_idx);            int*   idx = (int*)p;
    cudaGetSymbolAddress(&p, g_AgT);            float* AgT = (float*)p;
    cudaGetSymbolAddress(&p, g_AuT);            float* AuT = (float*)p;
    cudaGetSymbolAddress(&p, g_tg);             float* tg  = (float*)p;
    cudaGetSymbolAddress(&p, g_tu);             float* tu  = (float*)p;
    cudaGetSymbolAddress(&p, g_G);              float* G   = (float*)p;
    cudaGetSymbolAddress(&p, g_H);              float* H   = (float*)p;
    cudaGetSymbolAddress(&p, g_logits_scratch); float* lsc = (float*)p;

    const long long down_elems = (long long)NTOK * DDIM;   // 16,777,216
    float* logits = ((long long)out_size >= down_elems + (long long)NTOK * NEXP)
                        ? (out + down_elems) : lsc;

    // 1. A_{gate,up}: [E,D,R] -> [D, E*R]
    transposeA_kernel<<<(NEXP * DDIM * RDIM + 255) / 256, 256>>>(Ag, Au, AgT, AuT);
    // 2. router logits + top-1 index
    router_kernel<<<NTOK / 8, 256>>>(x, rw, idx, logits);
    // 3. masked LoRA activations: t = x @ A_T, zeroed outside selected expert block
    gemm_kernel<DDIM, DDIM, ERD, 3>
        <<<dim3(ERD / 128, NTOK / 128), 256>>>(x, nullptr, AgT, nullptr, idx, nullptr, tg);
    gemm_kernel<DDIM, DDIM, ERD, 3>
        <<<dim3(ERD / 128, NTOK / 128), 256>>>(x, nullptr, AuT, nullptr, idx, nullptr, tu);
    // 4. gate = [x | tg] @ [W_gate ; B_gate]   (K = 2304)
    gemm_kernel<DDIM + ERD, DDIM, IDIM, 0>
        <<<dim3(IDIM / 128, NTOK / 128), 256>>>(x, tg, Wg, Bg, nullptr, nullptr, G);
    // 5. H = silu(gate) * ([x | tu] @ [W_up ; B_up])
    gemm_kernel<DDIM + ERD, DDIM, IDIM, 1>
        <<<dim3(IDIM / 128, NTOK / 128), 256>>>(x, tu, Wu, Bu, nullptr, G, H);
    // 6. down = H @ W_down
    gemm_kernel<IDIM, IDIM, DDIM, 0>
        <<<dim3(DDIM / 128, NTOK / 128), 256>>>(H, nullptr, Wd, nullptr, nullptr, nullptr, out);
}

// round 10
// speedup vs baseline: 1.0003x; 1.0003x over previous
#include <cuda_runtime.h>
#include <cuda_bf16.h>

typedef unsigned long long ull;

#define NTOK 8192   // B*T
#define DDIM 2048
#define NEXP 8
#define IDIM 6144
#define RDIM 32
#define ERD  256    // NEXP*RDIM

// ---------------- scratch (static device allocations are the sanctioned path) ----
__device__ int   g_idx[NTOK];
__device__ float g_AgT[DDIM * ERD];           // A_gate transposed to [D, E*R]
__device__ float g_AuT[DDIM * ERD];
__device__ float g_tg[NTOK * ERD];            // masked lora activations (gate)
__device__ float g_tu[NTOK * ERD];            // masked lora activations (up)
__device__ float g_G[(size_t)NTOK * IDIM];    // gate pre-activation
__device__ float g_H[(size_t)NTOK * IDIM];    // silu(gate)*up
__device__ float g_logits_scratch[NTOK * NEXP];

// ---------------- f32x2 helpers (Blackwell packed fp32) --------------------------
__device__ __forceinline__ ull pk2(float x, float y) {
    ull r;
    asm("mov.b64 %0, {%1,%2};" : "=l"(r) : "f"(x), "f"(y));
    return r;
}
__device__ __forceinline__ void upk2(ull v, float& x, float& y) {
    asm("mov.b64 {%0,%1}, %2;" : "=f"(x), "=f"(y) : "l"(v));
}
__device__ __forceinline__ void fma2(ull& d, ull a, ull b) {
    asm("fma.rn.f32x2 %0, %1, %2, %0;" : "+l"(d) : "l"(a), "l"(b));
}

// ---------------- router: logits + argmax (first-max, matches jnp.argmax) --------
__global__ void router_kernel(const float* __restrict__ x,
                              const float* __restrict__ rw,
                              int* __restrict__ idx,
                              float* __restrict__ logits) {
    int gwarp = (blockIdx.x * blockDim.x + threadIdx.x) >> 5;
    int lane = threadIdx.x & 31;
    if (gwarp >= NTOK) return;
    const float* xp = x + (size_t)gwarp * DDIM;
    float acc[NEXP];
#pragma unroll
    for (int e = 0; e < NEXP; e++) acc[e] = 0.f;
    for (int d = lane; d < DDIM; d += 32) {
        float xv = xp[d];
        const float4* w4 = reinterpret_cast<const float4*>(rw + (size_t)d * NEXP);
        float4 w0 = w4[0], w1 = w4[1];
        acc[0] += xv * w0.x; acc[1] += xv * w0.y;
        acc[2] += xv * w0.z; acc[3] += xv * w0.w;
        acc[4] += xv * w1.x; acc[5] += xv * w1.y;
        acc[6] += xv * w1.z; acc[7] += xv * w1.w;
    }
#pragma unroll
    for (int e = 0; e < NEXP; e++) {
#pragma unroll
        for (int off = 16; off > 0; off >>= 1)
            acc[e] += __shfl_xor_sync(0xffffffffu, acc[e], off);
    }
    if (lane == 0) {
        int best = 0; float bv = acc[0];
#pragma unroll
        for (int e = 1; e < NEXP; e++)
            if (acc[e] > bv) { bv = acc[e]; best = e; }
        idx[gwarp] = best;
#pragma unroll
        for (int e = 0; e < NEXP; e++) logits[gwarp * NEXP + e] = acc[e];
    }
}

// ---------------- transpose A: [E, D, R] -> [D, E*R] -----------------------------
__global__ void transposeA_kernel(const float* __restrict__ Ag,
                                  const float* __restrict__ Au,
                                  float* __restrict__ AgT,
                                  float* __restrict__ AuT) {
    int i = blockIdx.x * blockDim.x + threadIdx.x;
    if (i >= NEXP * DDIM * RDIM) return;
    int r = i & (RDIM - 1);
    int d = (i >> 5) & (DDIM - 1);   // D*R = 65536 = 2^16, R = 32 = 2^5
    int e = i >> 16;
    int o = d * ERD + e * RDIM + r;
    AgT[o] = Ag[i];
    AuT[o] = Au[i];
}

// ---------------- generic SGEMM (f32x2), 128x128x16 tile, 8x8/thread -------------
// C[M,ND] = concat_K(A1[M,K1], A2[M,K2]) @ concat_K(B1[K1,ND], B2[K2,ND])
// MODE 0: plain store
// MODE 1: out = silu(Gprev) * acc          (fused SwiGLU)
// MODE 3: out = acc masked to token's expert (column block of 32 = expert id)
template<int KTOT, int K1, int ND, int MODE>
__global__ void __launch_bounds__(256)
gemm_kernel(const float* __restrict__ A1,
            const float* __restrict__ A2,
            const float* __restrict__ B1,
            const float* __restrict__ B2,
            const int* __restrict__ idx,
            const float* __restrict__ Gprev,
            float* __restrict__ out) {
    constexpr int BM = 128, BN = 128, BK = 16;
    constexpr int K2 = KTOT - K1;
    // A staged as duplicated (a,a) 64-bit pairs, row padded to 130 (1040B: 16B-aligned,
    // bank-shifted) so inner-loop reads need zero MOVs and stores are conflict-light.
    __shared__ ull   As2[BK][BM + 2];
    __shared__ float Bs[BK][BN];

    const int tid = threadIdx.x;
    const int row0 = blockIdx.y * BM;
    const int col0 = blockIdx.x * BN;
    const int tr = tid >> 4;          // 0..15
    const int tc = tid & 15;          // 0..15

    const int a_r = tid >> 2;         // 0..63
    const int a_c = (tid & 3) << 2;   // 0,4,8,12
    const int b_r = tid >> 5;         // 0..7
    const int b_c = (tid & 31) << 2;  // 0..124

    ull acc[8][4];
#pragma unroll
    for (int i = 0; i < 8; i++)
#pragma unroll
        for (int j = 0; j < 4; j++) acc[i][j] = 0ull;

    float4 aReg[2], bReg[2];

    auto loadAB = [&](int kc) {
#pragma unroll
        for (int it = 0; it < 2; it++) {
            int r = row0 + it * 64 + a_r;
            const float* pa;
            if (K2 == 0 || kc < K1)
                pa = A1 + (size_t)r * K1 + kc + a_c;
            else
                pa = A2 + (size_t)r * K2 + (kc - K1) + a_c;
            aReg[it] = *reinterpret_cast<const float4*>(pa);
        }
#pragma unroll
        for (int it = 0; it < 2; it++) {
            int kr = kc + it * 8 + b_r;
            const float* pb;
            if (K2 == 0 || kc < K1)
                pb = B1 + (size_t)kr * ND + col0 + b_c;
            else
                pb = B2 + (size_t)(kr - K1) * ND + col0 + b_c;
            bReg[it] = *reinterpret_cast<const float4*>(pb);
        }
    };

    loadAB(0);

    for (int kc = 0;;) {
        // commit prefetched tiles to smem
#pragma unroll
        for (int it = 0; it < 2; it++) {
            int r = it * 64 + a_r;
            As2[a_c + 0][r] = pk2(aReg[it].x, aReg[it].x);
            As2[a_c + 1][r] = pk2(aReg[it].y, aReg[it].y);
            As2[a_c + 2][r] = pk2(aReg[it].z, aReg[it].z);
            As2[a_c + 3][r] = pk2(aReg[it].w, aReg[it].w);
            *reinterpret_cast<float4*>(&Bs[it * 8 + b_r][b_c]) = bReg[it];
        }
        __syncthreads();

        int knext = kc + BK;
        if (knext < KTOT) loadAB(knext);

#pragma unroll
        for (int k = 0; k < BK; k++) {
            ulonglong2 aq0 = *reinterpret_cast<const ulonglong2*>(&As2[k][tr * 4]);
            ulonglong2 aq1 = *reinterpret_cast<const ulonglong2*>(&As2[k][tr * 4 + 2]);
            ulonglong2 aq2 = *reinterpret_cast<const ulonglong2*>(&As2[k][64 + tr * 4]);
            ulonglong2 aq3 = *reinterpret_cast<const ulonglong2*>(&As2[k][64 + tr * 4 + 2]);
            ulonglong2 bq0 = *reinterpret_cast<const ulonglong2*>(&Bs[k][tc * 4]);
            ulonglong2 bq1 = *reinterpret_cast<const ulonglong2*>(&Bs[k][64 + tc * 4]);
            ull a2[8] = {aq0.x, aq0.y, aq1.x, aq1.y, aq2.x, aq2.y, aq3.x, aq3.y};
            ull b2[4] = {bq0.x, bq0.y, bq1.x, bq1.y};
#pragma unroll
            for (int i = 0; i < 8; i++)
#pragma unroll
                for (int j = 0; j < 4; j++) fma2(acc[i][j], a2[i], b2[j]);
        }

        if (knext >= KTOT) break;
        __syncthreads();
        kc = knext;
    }

    // epilogue
    const int cbase0 = col0 + tc * 4;
    const int cbase1 = col0 + 64 + tc * 4;
    const int ce0 = cbase0 >> 5;    // expert id of column block (MODE 3)
    const int ce1 = cbase1 >> 5;

#pragma unroll
    for (int i = 0; i < 8; i++) {
        int row = row0 + (i < 4 ? tr * 4 + i : 64 + tr * 4 + (i - 4));
        float c[8];
        upk2(acc[i][0], c[0], c[1]);
        upk2(acc[i][1], c[2], c[3]);
        upk2(acc[i][2], c[4], c[5]);
        upk2(acc[i][3], c[6], c[7]);
        size_t base0 = (size_t)row * ND + cbase0;
        size_t base1 = (size_t)row * ND + cbase1;
        if (MODE == 3) {
            int e = idx[row];
            float k0 = (e == ce0) ? 1.f : 0.f;
            float k1 = (e == ce1) ? 1.f : 0.f;
#pragma unroll
            for (int j = 0; j < 4; j++) { c[j] *= k0; c[4 + j] *= k1; }
        }
        if (MODE == 1) {
#pragma unroll
            for (int j = 0; j < 4; j++) {
                float g = Gprev[base0 + j];
                c[j] *= g / (1.f + __expf(-g));
            }
#pragma unroll
            for (int j = 0; j < 4; j++) {
                float g = Gprev[base1 + j];
                c[4 + j] *= g / (1.f + __expf(-g));
            }
        }
        *reinterpret_cast<float4*>(out + base0) = make_float4(c[0], c[1], c[2], c[3]);
        *reinterpret_cast<float4*>(out + base1) = make_float4(c[4], c[5], c[6], c[7]);
    }
}

// ---------------- launch ----------------------------------------------------------
extern "C" void kernel_launch(void* const* d_in, const int* in_sizes, int n_in,
                              void* d_out, int out_size) {
    const float* x  = (const float*)d_in[0];
    const float* rw = (const float*)d_in[1];
    const float* Ag = (const float*)d_in[2];
    const float* Bg = (const float*)d_in[3];   // [E,R,I] == [256, 6144]
    const float* Au = (const float*)d_in[4];
    const float* Bu = (const float*)d_in[5];
    const float* Wg = (const float*)d_in[6];
    const float* Wu = (const float*)d_in[7];
    const float* Wd = (const float*)d_in[8];
    float* out = (float*)d_out;

    void* p;
    cudaGetSymbolAddress(&p, g_idx);            int*   idx = (int*)p;
    cudaGetSymbolAddress(&p, g_AgT);            float* AgT = (float*)p;
    cudaGetSymbolAddress(&p, g_AuT);            float* AuT = (float*)p;
    cudaGetSymbolAddress(&p, g_tg);             float* tg  = (float*)p;
    cudaGetSymbolAddress(&p, g_tu);             float* tu  = (float*)p;
    cudaGetSymbolAddress(&p, g_G);              float* G   = (float*)p;
    cudaGetSymbolAddress(&p, g_H);              float* H   = (float*)p;
    cudaGetSymbolAddress(&p, g_logits_scratch); float* lsc = (float*)p;

    const long long down_elems = (long long)NTOK * DDIM;   // 16,777,216
    float* logits = ((long long)out_size >= down_elems + (long long)NTOK * NEXP)
                        ? (out + down_elems) : lsc;

    // 1. A_{gate,up}: [E,D,R] -> [D, E*R]
    transposeA_kernel<<<(NEXP * DDIM * RDIM + 255) / 256, 256>>>(Ag, Au, AgT, AuT);
    // 2. router logits + top-1 index
    router_kernel<<<NTOK / 8, 256>>>(x, rw, idx, logits);
    // 3. masked LoRA activations: t = x @ A_T, zeroed outside selected expert block
    gemm_kernel<DDIM, DDIM, ERD, 3>
        <<<dim3(ERD / 128, NTOK / 128), 256>>>(x, nullptr, AgT, nullptr, idx, nullptr, tg);
    gemm_kernel<DDIM, DDIM, ERD, 3>
        <<<dim3(ERD / 128, NTOK / 128), 256>>>(x, nullptr, AuT, nullptr, idx, nullptr, tu);
    // 4. gate = [x | tg] @ [W_gate ; B_gate]   (K = 2304)
    gemm_kernel<DDIM + ERD, DDIM, IDIM, 0>
        <<<dim3(IDIM / 128, NTOK / 128), 256>>>(x, tg, Wg, Bg, nullptr, nullptr, G);
    // 5. H = silu(gate) * ([x | tu] @ [W_up ; B_up])
    gemm_kernel<DDIM + ERD, DDIM, IDIM, 1>
        <<<dim3(IDIM / 128, NTOK / 128), 256>>>(x, tu, Wu, Bu, nullptr, G, H);
    // 6. down = H @ W_down
    gemm_kernel<IDIM, IDIM, DDIM, 0>
        <<<dim3(DDIM / 128, NTOK / 128), 256>>>(H, nullptr, Wd, nullptr, nullptr, nullptr, out);
}